// round 1
// baseline (speedup 1.0000x reference)
#include <cuda_runtime.h>
#include <cuda_bf16.h>
#include <math.h>

// NTXentLoss fused: normalize -> (zj @ zi^T)/T with masked online logsumexp -> mean
// B=8192, D=128, T=0.1, idx scalar (0), labels int64.

#define B_SZ 8192
#define D_SZ 128
#define TM 64        // rows per CTA
#define TN 128       // cols per tile
#define PAD 132      // padded row stride in floats (132 mod 32 == 4 -> conflict-free LDS.128)

__device__ float g_zi[B_SZ * D_SZ];
__device__ float g_zj[B_SZ * D_SZ];   // pre-scaled by 1/T
__device__ float g_row_loss[B_SZ];

// ---------------- Kernel 1: L2 normalize (zj also scaled by 1/T = 10) --------
__global__ void ntx_norm_kernel(const float* __restrict__ zis,
                                const float* __restrict__ zjs) {
    int warp = (blockIdx.x * blockDim.x + threadIdx.x) >> 5;
    int lane = threadIdx.x & 31;
    if (warp >= 2 * B_SZ) return;
    bool isZj = warp >= B_SZ;
    int row = isZj ? warp - B_SZ : warp;
    const float* src = isZj ? zjs : zis;
    float* dst = isZj ? g_zj : g_zi;

    float4 v = ((const float4*)(src + (size_t)row * D_SZ))[lane];
    float ss = v.x * v.x + v.y * v.y + v.z * v.z + v.w * v.w;
#pragma unroll
    for (int o = 16; o; o >>= 1) ss += __shfl_xor_sync(0xFFFFFFFFu, ss, o);
    float sc = rsqrtf(ss) * (isZj ? 10.0f : 1.0f);
    v.x *= sc; v.y *= sc; v.z *= sc; v.w *= sc;
    ((float4*)(dst + (size_t)row * D_SZ))[lane] = v;
}

// ---------------- Kernel 2: fused GEMM + masked online logsumexp -------------
__global__ __launch_bounds__(256, 1)
void ntx_main_kernel(const long long* __restrict__ ilab,
                     const long long* __restrict__ jlab,
                     const int* __restrict__ idxp) {
    extern __shared__ float sm[];
    float* s_zj  = sm;                              // TM * PAD
    float* s_zi  = sm + TM * PAD;                   // TN * PAD
    int*   s_il  = (int*)(s_zi + TN * PAD);         // TN
    float* s_pos = (float*)(s_il + TN);             // TM

    const int tid = threadIdx.x;
    const int tx = tid & 15;        // column group 0..15
    const int ty = tid >> 4;        // row group 0..15
    const int rowBase = blockIdx.x * TM;
    const int idxv = idxp[0];       // low 32 bits (value is small nonneg)

    // Load resident zj tile (TM rows x 128)
    for (int i = tid; i < TM * (D_SZ / 4); i += 256) {
        int r = i >> 5, k4 = i & 31;
        float4 v = ((const float4*)(g_zj + (size_t)(rowBase + r) * D_SZ))[k4];
        *(float4*)(s_zj + r * PAD + k4 * 4) = v;
    }
    if (tid < TM) s_pos[tid] = 0.0f;

    int jl[4]; int pc[4];
    float m[4], s[4];
#pragma unroll
    for (int rr = 0; rr < 4; rr++) {
        int gr = rowBase + ty * 4 + rr;
        jl[rr] = (int)jlab[gr];
        int p = idxv + gr;                      // jax clamps OOB gathers
        pc[rr] = p < 0 ? 0 : (p > B_SZ - 1 ? B_SZ - 1 : p);
        m[rr] = -INFINITY;
        s[rr] = 0.0f;
    }
    __syncthreads();

    for (int cb = 0; cb < B_SZ; cb += TN) {
        // Load zi tile (TN rows x 128) + labels
        for (int i = tid; i < TN * (D_SZ / 4); i += 256) {
            int r = i >> 5, k4 = i & 31;
            float4 v = ((const float4*)(g_zi + (size_t)(cb + r) * D_SZ))[k4];
            *(float4*)(s_zi + r * PAD + k4 * 4) = v;
        }
        if (tid < TN) s_il[tid] = (int)ilab[cb + tid];
        __syncthreads();

        float acc[4][8];
#pragma unroll
        for (int rr = 0; rr < 4; rr++)
#pragma unroll
            for (int cc = 0; cc < 8; cc++) acc[rr][cc] = 0.0f;

#pragma unroll 2
        for (int k = 0; k < D_SZ; k += 4) {
            float4 a[4];
#pragma unroll
            for (int rr = 0; rr < 4; rr++)
                a[rr] = *(const float4*)(s_zj + (ty * 4 + rr) * PAD + k);
            float4 b[8];
#pragma unroll
            for (int cc = 0; cc < 8; cc++)
                b[cc] = *(const float4*)(s_zi + (cc * 16 + tx) * PAD + k);
#pragma unroll
            for (int rr = 0; rr < 4; rr++)
#pragma unroll
                for (int cc = 0; cc < 8; cc++) {
                    acc[rr][cc] += a[rr].x * b[cc].x;
                    acc[rr][cc] += a[rr].y * b[cc].y;
                    acc[rr][cc] += a[rr].z * b[cc].z;
                    acc[rr][cc] += a[rr].w * b[cc].w;
                }
        }

        // Epilogue: masked online logsumexp per thread-owned slice
#pragma unroll
        for (int cc = 0; cc < 8; cc++) {
            int lc = cc * 16 + tx;
            int lab = s_il[lc];
            int gc = cb + lc;
#pragma unroll
            for (int rr = 0; rr < 4; rr++) {
                float l = acc[rr][cc];
                if (gc == pc[rr]) s_pos[ty * 4 + rr] = l;   // unique writer
                if (lab != jl[rr]) {
                    if (l <= m[rr]) {
                        s[rr] += __expf(l - m[rr]);
                    } else {
                        s[rr] = s[rr] * __expf(m[rr] - l) + 1.0f;
                        m[rr] = l;
                    }
                }
            }
        }
        __syncthreads();  // protect s_zi / s_il before next tile load
    }

    // Cross-thread combine (16 partials per row), reusing s_zi space
    float* s_m = s_zi;               // TM * 17
    float* s_sv = s_zi + TM * 17;    // TM * 17
#pragma unroll
    for (int rr = 0; rr < 4; rr++) {
        s_m[(ty * 4 + rr) * 17 + tx] = m[rr];
        s_sv[(ty * 4 + rr) * 17 + tx] = s[rr];
    }
    __syncthreads();

    if (tid < TM) {
        float M = -INFINITY;
#pragma unroll
        for (int t = 0; t < 16; t++) M = fmaxf(M, s_m[tid * 17 + t]);
        float S = 0.0f;
#pragma unroll
        for (int t = 0; t < 16; t++) {
            float mk = s_m[tid * 17 + t];
            float sk = s_sv[tid * 17 + t];
            S += sk * __expf(mk - M);     // sk==0 when mk==-inf -> contributes 0
        }
        float pos = s_pos[tid];
        float M2 = fmaxf(M, pos);         // pos finite -> M2 finite
        float denom = __expf(pos - M2) + S * __expf(M - M2);
        g_row_loss[rowBase + tid] = M2 + logf(denom) - pos;
    }
}

// ---------------- Kernel 3: deterministic final reduction --------------------
__global__ void ntx_reduce_kernel(float* __restrict__ out) {
    __shared__ float r[256];
    float a = 0.0f;
    for (int i = threadIdx.x; i < B_SZ; i += 256) a += g_row_loss[i];
    r[threadIdx.x] = a;
    __syncthreads();
    for (int o = 128; o; o >>= 1) {
        if (threadIdx.x < o) r[threadIdx.x] += r[threadIdx.x + o];
        __syncthreads();
    }
    if (threadIdx.x == 0) out[0] = r[0] / (float)B_SZ;
}

extern "C" void kernel_launch(void* const* d_in, const int* in_sizes, int n_in,
                              void* d_out, int out_size) {
    const float* zis = (const float*)d_in[0];
    const float* zjs = (const float*)d_in[1];
    const long long* ilab = (const long long*)d_in[2];
    const long long* jlab = (const long long*)d_in[3];
    // d_in[4] = weights: mathematically cancels ((loss*w)/w), unused
    const int* idxp = (const int*)d_in[5];   // low 32 bits of the scalar
    float* out = (float*)d_out;

    size_t smem_bytes = (size_t)(TM * PAD + TN * PAD) * sizeof(float)
                        + TN * sizeof(int) + TM * sizeof(float);
    cudaFuncSetAttribute(ntx_main_kernel,
                         cudaFuncAttributeMaxDynamicSharedMemorySize,
                         (int)smem_bytes);

    ntx_norm_kernel<<<(2 * B_SZ * 32) / 256, 256>>>(zis, zjs);
    ntx_main_kernel<<<B_SZ / TM, 256, smem_bytes>>>(ilab, jlab, idxp);
    ntx_reduce_kernel<<<1, 256>>>(out);
}

// round 3
// speedup vs baseline: 7.8793x; 7.8793x over previous
#include <cuda_runtime.h>
#include <cuda_bf16.h>
#include <math.h>
#include <stdint.h>

// NTXentLoss: normalize -> (zj @ zi^T)/T -> per-row masked sum(exp) -> log - pos -> mean
// B=8192, D=128, T=0.1. mma.sync bf16 GEMM (register accum) + FFMA-poly exp epilogue.

#define B_SZ 8192
#define D_SZ 128

__device__ float         g_zi32[B_SZ * D_SZ];
__device__ float         g_zj32[B_SZ * D_SZ];
__device__ __nv_bfloat16 g_zib[B_SZ * D_SZ];
__device__ __nv_bfloat16 g_zjb[B_SZ * D_SZ];
__device__ float         g_pos[B_SZ];
__device__ float         g_part[64 * B_SZ];   // [colBlock][row]
__device__ float         g_blocksum[64];

// exp(10*a) = 2^(a*C1), C1 = 10*log2(e); magic-number range reduction
#define EXP_C1    14.42695040888963f
#define EXP_MAGIC 12582912.0f            // 1.5 * 2^23

__device__ __forceinline__ float exp10x(float a) {
    float t = fmaf(a, EXP_C1, EXP_MAGIC);
    uint32_t kb = __float_as_uint(t) << 23;          // n << 23 exactly
    float r = fmaf(a, EXP_C1, EXP_MAGIC - t);        // a*C1 - n, in [-0.5, 0.5]
    float q = fmaf(r, 0.009618129107628477f, 0.05550410866482158f);
    q = fmaf(r, q, 0.2402265069591007f);
    q = fmaf(r, q, 0.6931471805599453f);
    float p = fmaf(r, q, 1.0f);
    return __uint_as_float(__float_as_uint(p) + kb); // p * 2^n
}

__device__ __forceinline__ uint32_t smem_u32(const void* p) {
    uint32_t a;
    asm("{ .reg .u64 t; cvta.to.shared.u64 t, %1; cvt.u32.u64 %0, t; }" : "=r"(a) : "l"(p));
    return a;
}
__device__ __forceinline__ void ldsm4(uint32_t* r, uint32_t addr) {
    asm volatile("ldmatrix.sync.aligned.m8n8.x4.shared.b16 {%0,%1,%2,%3}, [%4];"
                 : "=r"(r[0]), "=r"(r[1]), "=r"(r[2]), "=r"(r[3]) : "r"(addr));
}
__device__ __forceinline__ void mma16816(float* d, const uint32_t* a, uint32_t b0, uint32_t b1) {
    asm volatile(
        "mma.sync.aligned.m16n8k16.row.col.f32.bf16.bf16.f32 "
        "{%0,%1,%2,%3}, {%4,%5,%6,%7}, {%8,%9}, {%0,%1,%2,%3};"
        : "+f"(d[0]), "+f"(d[1]), "+f"(d[2]), "+f"(d[3])
        : "r"(a[0]), "r"(a[1]), "r"(a[2]), "r"(a[3]), "r"(b0), "r"(b1));
}

// smem layout (bytes)
#define SM_A    0          // 128x128 bf16, xor-swizzled (32KB)
#define SM_B    32768      // 128x128 bf16, xor-swizzled (32KB)
#define SM_IL   65536      // int[128] column labels
#define SM_JL   66048      // int[128] row labels
#define SM_PART 66560      // float[128][4]
#define SM_TOT  68608

// ---------------- Kernel 1: normalize, write f32 + bf16 copies --------------
__global__ void ntx_norm_kernel(const float* __restrict__ zis,
                                const float* __restrict__ zjs) {
    int warp = (blockIdx.x * blockDim.x + threadIdx.x) >> 5;
    int lane = threadIdx.x & 31;
    if (warp >= 2 * B_SZ) return;
    bool isZj = warp >= B_SZ;
    int row = isZj ? warp - B_SZ : warp;
    const float* src = isZj ? zjs : zis;
    float* d32 = isZj ? g_zj32 : g_zi32;
    __nv_bfloat16* db = isZj ? g_zjb : g_zib;

    float4 v = ((const float4*)(src + (size_t)row * D_SZ))[lane];
    float ss = v.x * v.x + v.y * v.y + v.z * v.z + v.w * v.w;
#pragma unroll
    for (int o = 16; o; o >>= 1) ss += __shfl_xor_sync(0xFFFFFFFFu, ss, o);
    float sc = rsqrtf(ss);
    v.x *= sc; v.y *= sc; v.z *= sc; v.w *= sc;
    ((float4*)(d32 + (size_t)row * D_SZ))[lane] = v;
    __nv_bfloat162 b01 = __nv_bfloat162(__float2bfloat16_rn(v.x), __float2bfloat16_rn(v.y));
    __nv_bfloat162 b23 = __nv_bfloat162(__float2bfloat16_rn(v.z), __float2bfloat16_rn(v.w));
    uint2 packed = make_uint2(*(uint32_t*)&b01, *(uint32_t*)&b23);
    ((uint2*)(db + (size_t)row * D_SZ))[lane] = packed;
}

// ---------------- Kernel 2: exact f32 positive logit per row ----------------
__global__ void ntx_pos_kernel(const int* __restrict__ idxp) {
    int warp = (blockIdx.x * blockDim.x + threadIdx.x) >> 5;
    int lane = threadIdx.x & 31;
    if (warp >= B_SZ) return;
    int p = idxp[0] + warp;
    p = p < 0 ? 0 : (p > B_SZ - 1 ? B_SZ - 1 : p);
    float4 a = ((const float4*)(g_zj32 + (size_t)warp * D_SZ))[lane];
    float4 b = ((const float4*)(g_zi32 + (size_t)p * D_SZ))[lane];
    float d = a.x * b.x + a.y * b.y + a.z * b.z + a.w * b.w;
#pragma unroll
    for (int o = 16; o; o >>= 1) d += __shfl_xor_sync(0xFFFFFFFFu, d, o);
    if (lane == 0) g_pos[warp] = d * 10.0f;
}

// ---------------- Kernel 3: mma.sync GEMM tile + fused masked exp-sum -------
__global__ __launch_bounds__(256, 2)
void ntx_main_kernel(const long long* __restrict__ ilab,
                     const long long* __restrict__ jlab) {
    extern __shared__ char smc[];
    const uint32_t sb = smem_u32(smc);
    const int tid = threadIdx.x;
    const int w = tid >> 5;
    const int l = tid & 31;
    const int wm = w >> 2;           // 0..1 (row band of 64)
    const int wn = w & 3;            // 0..3 (col band of 32)

    const int rowBase = blockIdx.y * 128;
    const int colBase = blockIdx.x * 128;

    int* s_il = (int*)(smc + SM_IL);
    int* s_jl = (int*)(smc + SM_JL);
    float* s_part = (float*)(smc + SM_PART);

    // ---- load tiles (xor-swizzled: chunk c of row r stored at c^(r&7)) ----
#pragma unroll
    for (int i = 0; i < 8; i++) {
        int idx = tid + i * 256;                 // 0..2047
        int r = idx >> 4, c = idx & 15;
        uint4 v = *(const uint4*)(g_zjb + (size_t)(rowBase + r) * D_SZ + c * 8);
        *(uint4*)(smc + SM_A + r * 256 + ((c ^ (r & 7)) << 4)) = v;
    }
#pragma unroll
    for (int i = 0; i < 8; i++) {
        int idx = tid + i * 256;
        int r = idx >> 4, c = idx & 15;
        uint4 v = *(const uint4*)(g_zib + (size_t)(colBase + r) * D_SZ + c * 8);
        *(uint4*)(smc + SM_B + r * 256 + ((c ^ (r & 7)) << 4)) = v;
    }
    if (tid < 128) s_il[tid] = (int)ilab[colBase + tid];
    else           s_jl[tid - 128] = (int)jlab[rowBase + tid - 128];
    __syncthreads();

    // ---- MMA: warp tile 64x32, 4 m-tiles x 4 n-tiles, K=128 in 8 steps ----
    float acc[4][4][4];
#pragma unroll
    for (int mt = 0; mt < 4; mt++)
#pragma unroll
        for (int nt = 0; nt < 4; nt++)
#pragma unroll
            for (int e = 0; e < 4; e++) acc[mt][nt][e] = 0.0f;

    const int rA = wm * 64 + (l & 15);           // ldmatrix A row (per mt: +16*mt)
    const int rB = wn * 32 + ((l >> 4) << 3) + (l & 7);  // B rows for n-pair
    const uint32_t aRowOff = (uint32_t)rA * 256;
    const uint32_t bRowOff = (uint32_t)rB * 256;
    const int cbA = l >> 4;                      // A chunk bit
    const int cbB = (l >> 3) & 1;                // B chunk bit
    const int sw = l & 7;

#pragma unroll
    for (int k = 0; k < 8; k++) {
        uint32_t a[4][4], b[2][4];
        uint32_t chA = (uint32_t)(((2 * k + cbA) ^ sw) << 4);
        uint32_t chB = (uint32_t)(((2 * k + cbB) ^ sw) << 4);
#pragma unroll
        for (int mt = 0; mt < 4; mt++)
            ldsm4(a[mt], sb + SM_A + aRowOff + (uint32_t)(mt * 16 * 256) + chA);
#pragma unroll
        for (int np = 0; np < 2; np++)
            ldsm4(b[np], sb + SM_B + bRowOff + (uint32_t)(np * 16 * 256) + chB);
#pragma unroll
        for (int mt = 0; mt < 4; mt++)
#pragma unroll
            for (int nt = 0; nt < 4; nt++)
                mma16816(acc[mt][nt], a[mt], b[nt >> 1][(nt & 1) * 2], b[nt >> 1][(nt & 1) * 2 + 1]);
    }

    // ---- epilogue: masked exp + per-row accumulation (all in registers) ----
#pragma unroll
    for (int mt = 0; mt < 4; mt++) {
        int rloc0 = wm * 64 + mt * 16 + (l >> 2);
        int rloc1 = rloc0 + 8;
        int jl0 = s_jl[rloc0];
        int jl1 = s_jl[rloc1];
        float racc0 = 0.0f, racc1 = 0.0f;
#pragma unroll
        for (int nt = 0; nt < 4; nt++) {
            int cloc = wn * 32 + nt * 8 + 2 * (l & 3);
            int2 cl = *(const int2*)(s_il + cloc);
            float e00 = exp10x(acc[mt][nt][0]);
            float e01 = exp10x(acc[mt][nt][1]);
            float e10 = exp10x(acc[mt][nt][2]);
            float e11 = exp10x(acc[mt][nt][3]);
            racc0 += (cl.x != jl0 ? e00 : 0.0f) + (cl.y != jl0 ? e01 : 0.0f);
            racc1 += (cl.x != jl1 ? e10 : 0.0f) + (cl.y != jl1 ? e11 : 0.0f);
        }
        racc0 += __shfl_xor_sync(0xFFFFFFFFu, racc0, 1);
        racc0 += __shfl_xor_sync(0xFFFFFFFFu, racc0, 2);
        racc1 += __shfl_xor_sync(0xFFFFFFFFu, racc1, 1);
        racc1 += __shfl_xor_sync(0xFFFFFFFFu, racc1, 2);
        if ((l & 3) == 0) {
            s_part[rloc0 * 4 + wn] = racc0;
            s_part[rloc1 * 4 + wn] = racc1;
        }
    }
    __syncthreads();

    if (tid < 128) {
        float s = s_part[tid * 4] + s_part[tid * 4 + 1] + s_part[tid * 4 + 2] + s_part[tid * 4 + 3];
        g_part[blockIdx.x * B_SZ + rowBase + tid] = s;
    }
}

// ---------------- Kernel 4a: per-row loss, per-block sum --------------------
__global__ void ntx_row_kernel() {
    __shared__ float r[128];
    int row = blockIdx.x * 128 + threadIdx.x;
    float pos = g_pos[row];
    float denom = expf(pos);
#pragma unroll 8
    for (int c = 0; c < 64; c++) denom += g_part[c * B_SZ + row];
    r[threadIdx.x] = logf(denom) - pos;
    __syncthreads();
    for (int o = 64; o; o >>= 1) {
        if (threadIdx.x < o) r[threadIdx.x] += r[threadIdx.x + o];
        __syncthreads();
    }
    if (threadIdx.x == 0) g_blocksum[blockIdx.x] = r[0];
}

// ---------------- Kernel 4b: deterministic final ----------------------------
__global__ void ntx_fin_kernel(float* __restrict__ out) {
    if (threadIdx.x == 0) {
        float s = 0.0f;
        for (int i = 0; i < 64; i++) s += g_blocksum[i];
        out[0] = s / (float)B_SZ;
    }
}

extern "C" void kernel_launch(void* const* d_in, const int* in_sizes, int n_in,
                              void* d_out, int out_size) {
    const float* zis = (const float*)d_in[0];
    const float* zjs = (const float*)d_in[1];
    const long long* ilab = (const long long*)d_in[2];
    const long long* jlab = (const long long*)d_in[3];
    // d_in[4] = weights: (loss*w)/w cancels, unused
    const int* idxp = (const int*)d_in[5];
    float* out = (float*)d_out;

    cudaFuncSetAttribute(ntx_main_kernel,
                         cudaFuncAttributeMaxDynamicSharedMemorySize, SM_TOT);

    ntx_norm_kernel<<<2048, 256>>>(zis, zjs);
    ntx_pos_kernel<<<1024, 256>>>(idxp);
    dim3 grid(64, 64);
    ntx_main_kernel<<<grid, 256, SM_TOT>>>(ilab, jlab);
    ntx_row_kernel<<<64, 128>>>();
    ntx_fin_kernel<<<1, 32>>>(out);
}

// round 4
// speedup vs baseline: 8.6501x; 1.0978x over previous
#include <cuda_runtime.h>
#include <cuda_bf16.h>
#include <math.h>
#include <stdint.h>

// NTXentLoss: normalize -> (zj @ zi^T)/T -> per-row masked sum(exp) -> log - pos -> mean
// B=8192, D=128, T=0.1. mma.sync bf16 GEMM (register accum) + MUFU.EX2 epilogue.

#define B_SZ 8192
#define D_SZ 128

__device__ float         g_zi32[B_SZ * D_SZ];
__device__ float         g_zj32[B_SZ * D_SZ];
__device__ __nv_bfloat16 g_zib[B_SZ * D_SZ];
__device__ __nv_bfloat16 g_zjb[B_SZ * D_SZ];
__device__ float         g_pos[B_SZ];
__device__ float         g_part[B_SZ * 64];   // [row][colBlock]
__device__ float         g_blocksum[1024];

#define EXP_C1 14.42695040888963f             // 10 * log2(e)

// exp(10*a) via single MUFU.EX2 (separate pipe from FFMA)
__device__ __forceinline__ float exp10m(float a) {
    float t = a * EXP_C1;
    float r;
    asm("ex2.approx.f32 %0, %1;" : "=f"(r) : "f"(t));
    return r;
}

__device__ __forceinline__ uint32_t smem_u32(const void* p) {
    uint32_t a;
    asm("{ .reg .u64 t; cvta.to.shared.u64 t, %1; cvt.u32.u64 %0, t; }" : "=r"(a) : "l"(p));
    return a;
}
__device__ __forceinline__ void ldsm4(uint32_t* r, uint32_t addr) {
    asm volatile("ldmatrix.sync.aligned.m8n8.x4.shared.b16 {%0,%1,%2,%3}, [%4];"
                 : "=r"(r[0]), "=r"(r[1]), "=r"(r[2]), "=r"(r[3]) : "r"(addr));
}
__device__ __forceinline__ void mma16816(float* d, const uint32_t* a, uint32_t b0, uint32_t b1) {
    asm volatile(
        "mma.sync.aligned.m16n8k16.row.col.f32.bf16.bf16.f32 "
        "{%0,%1,%2,%3}, {%4,%5,%6,%7}, {%8,%9}, {%0,%1,%2,%3};"
        : "+f"(d[0]), "+f"(d[1]), "+f"(d[2]), "+f"(d[3])
        : "r"(a[0]), "r"(a[1]), "r"(a[2]), "r"(a[3]), "r"(b0), "r"(b1));
}

// smem layout (bytes)
#define SM_A    0          // 128x128 bf16, xor-swizzled (32KB)
#define SM_B    32768      // 128x128 bf16, xor-swizzled (32KB)
#define SM_IL   65536      // int[128] column labels
#define SM_JL   66048      // int[128] row labels
#define SM_PART 66560      // float[128][4]
#define SM_TOT  68608

// ---------------- Kernel 1: normalize (4 rows/warp, MLP=4), f32 + bf16 ------
__global__ void ntx_norm_kernel(const float* __restrict__ zis,
                                const float* __restrict__ zjs) {
    int warp = (blockIdx.x * blockDim.x + threadIdx.x) >> 5;
    int lane = threadIdx.x & 31;
    int sub = lane & 7;            // position within row (8 lanes per row)
    int rq  = lane >> 3;           // which of the 4 rows this lane serves
    int row = warp * 4 + rq;       // global row in [0, 16384)
    if (row >= 2 * B_SZ) return;
    bool isZj = row >= B_SZ;
    int r = isZj ? row - B_SZ : row;
    const float* src = (isZj ? zjs : zis) + (size_t)r * D_SZ;
    float* d32 = (isZj ? g_zj32 : g_zi32) + (size_t)r * D_SZ;
    __nv_bfloat16* db = (isZj ? g_zjb : g_zib) + (size_t)r * D_SZ;

    float4 v[4];
#pragma unroll
    for (int q = 0; q < 4; q++) v[q] = ((const float4*)src)[sub + 8 * q];
    float ss = 0.0f;
#pragma unroll
    for (int q = 0; q < 4; q++)
        ss += v[q].x * v[q].x + v[q].y * v[q].y + v[q].z * v[q].z + v[q].w * v[q].w;
    ss += __shfl_xor_sync(0xFFFFFFFFu, ss, 1);
    ss += __shfl_xor_sync(0xFFFFFFFFu, ss, 2);
    ss += __shfl_xor_sync(0xFFFFFFFFu, ss, 4);
    float sc = rsqrtf(ss);
#pragma unroll
    for (int q = 0; q < 4; q++) {
        v[q].x *= sc; v[q].y *= sc; v[q].z *= sc; v[q].w *= sc;
        ((float4*)d32)[sub + 8 * q] = v[q];
        __nv_bfloat162 b01 = __nv_bfloat162(__float2bfloat16_rn(v[q].x), __float2bfloat16_rn(v[q].y));
        __nv_bfloat162 b23 = __nv_bfloat162(__float2bfloat16_rn(v[q].z), __float2bfloat16_rn(v[q].w));
        ((uint2*)db)[sub + 8 * q] = make_uint2(*(uint32_t*)&b01, *(uint32_t*)&b23);
    }
}

// ---------------- Kernel 2: exact f32 positive logit per row ----------------
__global__ void ntx_pos_kernel(const int* __restrict__ idxp) {
    int warp = (blockIdx.x * blockDim.x + threadIdx.x) >> 5;
    int lane = threadIdx.x & 31;
    if (warp >= B_SZ) return;
    int p = idxp[0] + warp;
    p = p < 0 ? 0 : (p > B_SZ - 1 ? B_SZ - 1 : p);
    float4 a = ((const float4*)(g_zj32 + (size_t)warp * D_SZ))[lane];
    float4 b = ((const float4*)(g_zi32 + (size_t)p * D_SZ))[lane];
    float d = a.x * b.x + a.y * b.y + a.z * b.z + a.w * b.w;
#pragma unroll
    for (int o = 16; o; o >>= 1) d += __shfl_xor_sync(0xFFFFFFFFu, d, o);
    if (lane == 0) g_pos[warp] = d * 10.0f;
}

// ---------------- Kernel 3: mma.sync GEMM tile + fused masked exp-sum -------
__global__ __launch_bounds__(256, 2)
void ntx_main_kernel(const long long* __restrict__ ilab,
                     const long long* __restrict__ jlab) {
    extern __shared__ char smc[];
    const uint32_t sb = smem_u32(smc);
    const int tid = threadIdx.x;
    const int w = tid >> 5;
    const int l = tid & 31;
    const int wm = w >> 2;           // 0..1 (row band of 64)
    const int wn = w & 3;            // 0..3 (col band of 32)

    const int rowBase = blockIdx.y * 128;
    const int colBase = blockIdx.x * 128;

    int* s_il = (int*)(smc + SM_IL);
    int* s_jl = (int*)(smc + SM_JL);
    float* s_part = (float*)(smc + SM_PART);

    // ---- load tiles (xor-swizzled: chunk c of row r stored at c^(r&7)) ----
#pragma unroll
    for (int i = 0; i < 8; i++) {
        int idx = tid + i * 256;                 // 0..2047
        int r = idx >> 4, c = idx & 15;
        uint4 v = *(const uint4*)(g_zjb + (size_t)(rowBase + r) * D_SZ + c * 8);
        *(uint4*)(smc + SM_A + r * 256 + ((c ^ (r & 7)) << 4)) = v;
    }
#pragma unroll
    for (int i = 0; i < 8; i++) {
        int idx = tid + i * 256;
        int r = idx >> 4, c = idx & 15;
        uint4 v = *(const uint4*)(g_zib + (size_t)(colBase + r) * D_SZ + c * 8);
        *(uint4*)(smc + SM_B + r * 256 + ((c ^ (r & 7)) << 4)) = v;
    }
    if (tid < 128) s_il[tid] = (int)ilab[colBase + tid];
    else           s_jl[tid - 128] = (int)jlab[rowBase + tid - 128];
    __syncthreads();

    // ---- MMA: warp tile 64x32, 4 m-tiles x 4 n-tiles, K=128 in 8 steps ----
    float acc[4][4][4];
#pragma unroll
    for (int mt = 0; mt < 4; mt++)
#pragma unroll
        for (int nt = 0; nt < 4; nt++)
#pragma unroll
            for (int e = 0; e < 4; e++) acc[mt][nt][e] = 0.0f;

    const int rA = wm * 64 + (l & 15);
    const int rB = wn * 32 + ((l >> 4) << 3) + (l & 7);
    const uint32_t aRowOff = (uint32_t)rA * 256;
    const uint32_t bRowOff = (uint32_t)rB * 256;
    const int cbA = l >> 4;
    const int cbB = (l >> 3) & 1;
    const int sw = l & 7;

#pragma unroll
    for (int k = 0; k < 8; k++) {
        uint32_t a[4][4], b[2][4];
        uint32_t chA = (uint32_t)(((2 * k + cbA) ^ sw) << 4);
        uint32_t chB = (uint32_t)(((2 * k + cbB) ^ sw) << 4);
#pragma unroll
        for (int mt = 0; mt < 4; mt++)
            ldsm4(a[mt], sb + SM_A + aRowOff + (uint32_t)(mt * 16 * 256) + chA);
#pragma unroll
        for (int np = 0; np < 2; np++)
            ldsm4(b[np], sb + SM_B + bRowOff + (uint32_t)(np * 16 * 256) + chB);
#pragma unroll
        for (int mt = 0; mt < 4; mt++)
#pragma unroll
            for (int nt = 0; nt < 4; nt++)
                mma16816(acc[mt][nt], a[mt], b[nt >> 1][(nt & 1) * 2], b[nt >> 1][(nt & 1) * 2 + 1]);
    }

    // ---- epilogue: MUFU exp + mask + per-row accumulation ----
#pragma unroll
    for (int mt = 0; mt < 4; mt++) {
        int rloc0 = wm * 64 + mt * 16 + (l >> 2);
        int rloc1 = rloc0 + 8;
        int jl0 = s_jl[rloc0];
        int jl1 = s_jl[rloc1];
        float racc0 = 0.0f, racc1 = 0.0f;
#pragma unroll
        for (int nt = 0; nt < 4; nt++) {
            int cloc = wn * 32 + nt * 8 + 2 * (l & 3);
            int2 cl = *(const int2*)(s_il + cloc);
            float e00 = exp10m(acc[mt][nt][0]);
            float e01 = exp10m(acc[mt][nt][1]);
            float e10 = exp10m(acc[mt][nt][2]);
            float e11 = exp10m(acc[mt][nt][3]);
            racc0 += (cl.x != jl0 ? e00 : 0.0f) + (cl.y != jl0 ? e01 : 0.0f);
            racc1 += (cl.x != jl1 ? e10 : 0.0f) + (cl.y != jl1 ? e11 : 0.0f);
        }
        racc0 += __shfl_xor_sync(0xFFFFFFFFu, racc0, 1);
        racc0 += __shfl_xor_sync(0xFFFFFFFFu, racc0, 2);
        racc1 += __shfl_xor_sync(0xFFFFFFFFu, racc1, 1);
        racc1 += __shfl_xor_sync(0xFFFFFFFFu, racc1, 2);
        if ((l & 3) == 0) {
            s_part[rloc0 * 4 + wn] = racc0;
            s_part[rloc1 * 4 + wn] = racc1;
        }
    }
    __syncthreads();

    if (tid < 128) {
        float s = s_part[tid * 4] + s_part[tid * 4 + 1] + s_part[tid * 4 + 2] + s_part[tid * 4 + 3];
        g_part[(size_t)(rowBase + tid) * 64 + blockIdx.x] = s;
    }
}

// ---------------- Kernel 4a: warp-per-row loss + per-block sum --------------
__global__ void ntx_row_kernel() {
    __shared__ float r[8];
    int w = threadIdx.x >> 5;
    int l = threadIdx.x & 31;
    int row = blockIdx.x * 8 + w;
    float s = g_part[(size_t)row * 64 + l] + g_part[(size_t)row * 64 + 32 + l];
#pragma unroll
    for (int o = 16; o; o >>= 1) s += __shfl_xor_sync(0xFFFFFFFFu, s, o);
    if (l == 0) {
        float pos = g_pos[row];
        float ep;
        asm("ex2.approx.f32 %0, %1;" : "=f"(ep) : "f"(pos * 1.4426950408889634f));
        r[w] = logf(s + ep) - pos;
    }
    __syncthreads();
    if (threadIdx.x == 0) {
        float a = 0.0f;
#pragma unroll
        for (int i = 0; i < 8; i++) a += r[i];
        g_blocksum[blockIdx.x] = a;
    }
}

// ---------------- Kernel 4b: deterministic final ----------------------------
__global__ void ntx_fin_kernel(float* __restrict__ out) {
    __shared__ float r[256];
    float a = 0.0f;
#pragma unroll
    for (int i = 0; i < 4; i++) a += g_blocksum[threadIdx.x * 4 + i];
    r[threadIdx.x] = a;
    __syncthreads();
    for (int o = 128; o; o >>= 1) {
        if (threadIdx.x < o) r[threadIdx.x] += r[threadIdx.x + o];
        __syncthreads();
    }
    if (threadIdx.x == 0) out[0] = r[0] / (float)B_SZ;
}

extern "C" void kernel_launch(void* const* d_in, const int* in_sizes, int n_in,
                              void* d_out, int out_size) {
    const float* zis = (const float*)d_in[0];
    const float* zjs = (const float*)d_in[1];
    const long long* ilab = (const long long*)d_in[2];
    const long long* jlab = (const long long*)d_in[3];
    // d_in[4] = weights: (loss*w)/w cancels, unused
    const int* idxp = (const int*)d_in[5];
    float* out = (float*)d_out;

    cudaFuncSetAttribute(ntx_main_kernel,
                         cudaFuncAttributeMaxDynamicSharedMemorySize, SM_TOT);

    ntx_norm_kernel<<<512, 256>>>(zis, zjs);          // 4096 warps x 4 rows
    ntx_pos_kernel<<<1024, 256>>>(idxp);
    dim3 grid(64, 64);
    ntx_main_kernel<<<grid, 256, SM_TOT>>>(ilab, jlab);
    ntx_row_kernel<<<1024, 256>>>();
    ntx_fin_kernel<<<1, 256>>>(out);
}